// round 2
// baseline (speedup 1.0000x reference)
#include <cuda_runtime.h>
#include <cuda_bf16.h>
#include <float.h>

// Problem shape (RLFrameSelector): x[B,T,F], W1[F,U], b1[U], W2[U,1], b2[1], k
#define BB 32
#define TT 2048
#define FF 512
#define UU 128
#define BT (BB * TT)      // 65536 frames
#define KC 64             // K-chunk (features per smem tile)
#define FR 64             // frames per block
#define NEG_BIG (-1.0e9f)

// Dynamic smem layout: xs [KC*FR] floats, ws [KC*UU] floats, nz [FR] ints
#define SMEM_XS_FLOATS (KC * FR)          // 4096 floats = 16384 B
#define SMEM_WS_FLOATS (KC * UU)          // 8192 floats = 32768 B
#define SMEM_BYTES ((SMEM_XS_FLOATS + SMEM_WS_FLOATS) * 4 + FR * 4)  // 49408 B

// Scratch (device globals: no allocation allowed)
__device__ float g_scores[BT];
__device__ int   g_sel[BT];

// ---------------- packed f32x2 helpers (Blackwell FFMA2) ----------------
__device__ __forceinline__ unsigned long long fma2(unsigned long long a,
                                                   unsigned long long b,
                                                   unsigned long long c) {
    unsigned long long d;
    asm("fma.rn.f32x2 %0, %1, %2, %3;" : "=l"(d) : "l"(a), "l"(b), "l"(c));
    return d;
}
__device__ __forceinline__ unsigned long long pack2(float v) {
    unsigned long long d;
    asm("mov.b64 %0, {%1, %1};" : "=l"(d) : "f"(v));
    return d;
}
__device__ __forceinline__ float2 unpack2(unsigned long long v) {
    float2 r;
    asm("mov.b64 {%0, %1}, %2;" : "=f"(r.x), "=f"(r.y) : "l"(v));
    return r;
}

// ---------------- Kernel 1: scores = relu(x@W1 + b1) @ W2 (masked) ----------
// Block: 256 threads, tile = 64 frames x 128 u. K-chunks of 64 features.
// Warp w owns frames [w*8, w*8+8); lane l owns u in [4l, 4l+4).
// Accumulators: 4 frame-pairs x 4 u as f32x2 (16 ull = 32 regs).
// x smem tile is XOR-swizzled: conflict-limited staging stores AND aligned
// broadcast 16B reads, with zero padding overhead.
__global__ __launch_bounds__(256, 3)
void scores_kernel(const float* __restrict__ x,
                   const float* __restrict__ W1,
                   const float* __restrict__ b1,
                   const float* __restrict__ W2) {
    extern __shared__ float sm[];
    float* xs = sm;                          // [f][frame^swz]  16KB
    float* ws = sm + SMEM_XS_FLOATS;         // [f][u]          32KB
    int*   nz = (int*)(sm + SMEM_XS_FLOATS + SMEM_WS_FLOATS);  // [FR]

    const int t = threadIdx.x;
    const int w = t >> 5;
    const int l = t & 31;
    const int w8 = w * 8;
    const int l4 = l * 4;
    const int frame_base = blockIdx.x * FR;

    if (t < FR) nz[t] = 0;

    unsigned long long acc[4][4];
#pragma unroll
    for (int m = 0; m < 4; ++m)
#pragma unroll
        for (int i = 0; i < 4; ++i) acc[m][i] = 0ull;

    for (int c = 0; c < FF / KC; ++c) {
        __syncthreads();
        // ---- stage x chunk: 64 frames x 64 features ----
#pragma unroll
        for (int r = 0; r < 4; ++r) {
            const int it = t + 256 * r;      // 0..1023
            const int fr = it >> 4;          // 0..63
            const int f4 = it & 15;          // 0..15  (feature group of 4)
            const float4 v = *(const float4*)&x[(size_t)(frame_base + fr) * FF + c * KC + 4 * f4];
            if (v.x != 0.f || v.y != 0.f || v.z != 0.f || v.w != 0.f) nz[fr] = 1;
            const int sw = (f4 & 7) << 2;    // swizzle = ((f>>2)&7)<<2
            const int fx = fr ^ sw;
            xs[(4 * f4 + 0) * FR + fx] = v.x;
            xs[(4 * f4 + 1) * FR + fx] = v.y;
            xs[(4 * f4 + 2) * FR + fx] = v.z;
            xs[(4 * f4 + 3) * FR + fx] = v.w;
        }
        // ---- stage W1 chunk (contiguous 32KB) ----
        {
            const float4* wg = (const float4*)&W1[(size_t)c * KC * UU];
            float4* wd = (float4*)ws;
#pragma unroll
            for (int r = 0; r < 8; ++r) wd[t + 256 * r] = wg[t + 256 * r];
        }
        __syncthreads();
        // ---- compute ----
#pragma unroll 8
        for (int f = 0; f < KC; ++f) {
            const int sw = ((f >> 2) & 7) << 2;
            const int rowb = f * FR;
            // frames w8..w8+3 and w8+4..w8+7 as two f32x2-pairs each (broadcast)
            const ulonglong2 pa = *(const ulonglong2*)&xs[rowb + (w8 ^ sw)];
            const ulonglong2 pb = *(const ulonglong2*)&xs[rowb + ((w8 + 4) ^ sw)];
            const float4 wv = *(const float4*)&ws[f * UU + l4];
            const unsigned long long wp0 = pack2(wv.x);
            const unsigned long long wp1 = pack2(wv.y);
            const unsigned long long wp2 = pack2(wv.z);
            const unsigned long long wp3 = pack2(wv.w);
            acc[0][0] = fma2(pa.x, wp0, acc[0][0]);
            acc[0][1] = fma2(pa.x, wp1, acc[0][1]);
            acc[0][2] = fma2(pa.x, wp2, acc[0][2]);
            acc[0][3] = fma2(pa.x, wp3, acc[0][3]);
            acc[1][0] = fma2(pa.y, wp0, acc[1][0]);
            acc[1][1] = fma2(pa.y, wp1, acc[1][1]);
            acc[1][2] = fma2(pa.y, wp2, acc[1][2]);
            acc[1][3] = fma2(pa.y, wp3, acc[1][3]);
            acc[2][0] = fma2(pb.x, wp0, acc[2][0]);
            acc[2][1] = fma2(pb.x, wp1, acc[2][1]);
            acc[2][2] = fma2(pb.x, wp2, acc[2][2]);
            acc[2][3] = fma2(pb.x, wp3, acc[2][3]);
            acc[3][0] = fma2(pb.y, wp0, acc[3][0]);
            acc[3][1] = fma2(pb.y, wp1, acc[3][1]);
            acc[3][2] = fma2(pb.y, wp2, acc[3][2]);
            acc[3][3] = fma2(pb.y, wp3, acc[3][3]);
        }
    }
    __syncthreads();

    // ---- epilogue: relu(+b1) * W2, reduce over u (lanes), write scores ----
    // b2 is omitted: it shifts every score equally and cannot change top-k.
    const float4 b1v = *(const float4*)&b1[l4];
    const float4 w2v = *(const float4*)&W2[l4];
    const float bb1[4] = {b1v.x, b1v.y, b1v.z, b1v.w};
    const float ww2[4] = {w2v.x, w2v.y, w2v.z, w2v.w};

#pragma unroll
    for (int m = 0; m < 4; ++m) {
        float sx = 0.f, sy = 0.f;
#pragma unroll
        for (int i = 0; i < 4; ++i) {
            const float2 a = unpack2(acc[m][i]);
            sx += fmaxf(a.x + bb1[i], 0.f) * ww2[i];
            sy += fmaxf(a.y + bb1[i], 0.f) * ww2[i];
        }
#pragma unroll
        for (int off = 16; off > 0; off >>= 1) {
            sx += __shfl_xor_sync(0xffffffffu, sx, off);
            sy += __shfl_xor_sync(0xffffffffu, sy, off);
        }
        if (l == 0) {
            const int frl = w8 + 2 * m;
            const int fr = frame_base + frl;
            g_scores[fr]     = nz[frl]     ? sx : NEG_BIG;
            g_scores[fr + 1] = nz[frl + 1] ? sy : NEG_BIG;
        }
    }
}

// ---------------- Kernel 2: per-row top-k (iterative argmax, index tiebreak) -
__global__ void topk_kernel(const int* __restrict__ kp) {
    __shared__ float sv[TT];
    __shared__ float bw[8];
    __shared__ int   bi[8];
    const int b = blockIdx.x;
    const int t = threadIdx.x;
    const float* row = g_scores + b * TT;
    int* selrow = g_sel + b * TT;

    for (int i = t; i < TT; i += 256) { sv[i] = row[i]; selrow[i] = 0; }
    __syncthreads();

    int k = kp[0];
    if (k <= 0 || k > TT) k = 64;

    for (int it = 0; it < k; ++it) {
        float best = -FLT_MAX;
        int bidx = TT;
        for (int i = t; i < TT; i += 256) {
            const float v = sv[i];
            if (v > best || (v == best && i < bidx)) { best = v; bidx = i; }
        }
#pragma unroll
        for (int off = 16; off > 0; off >>= 1) {
            const float ov = __shfl_xor_sync(0xffffffffu, best, off);
            const int   oi = __shfl_xor_sync(0xffffffffu, bidx, off);
            if (ov > best || (ov == best && oi < bidx)) { best = ov; bidx = oi; }
        }
        if ((t & 31) == 0) { bw[t >> 5] = best; bi[t >> 5] = bidx; }
        __syncthreads();
        if (t == 0) {
            float b0 = bw[0]; int i0 = bi[0];
#pragma unroll
            for (int j = 1; j < 8; ++j)
                if (bw[j] > b0 || (bw[j] == b0 && bi[j] < i0)) { b0 = bw[j]; i0 = bi[j]; }
            sv[i0] = -FLT_MAX;
            selrow[i0] = 1;
        }
        __syncthreads();
    }
}

// ---------------- Kernel 3: out = sel ? x : 0 (skip x read when unselected) --
__global__ __launch_bounds__(128)
void scatter_kernel(const float* __restrict__ x, float* __restrict__ out) {
    const int frame = blockIdx.x;
    const int t = threadIdx.x;
    const int s = g_sel[frame];
    const size_t base = (size_t)frame * FF + (size_t)t * 4;
    float4* o = (float4*)(out + base);
    if (s) *o = *(const float4*)(x + base);
    else   *o = make_float4(0.f, 0.f, 0.f, 0.f);
}

extern "C" void kernel_launch(void* const* d_in, const int* in_sizes, int n_in,
                              void* d_out, int out_size) {
    const float* x  = (const float*)d_in[0];
    const float* W1 = (const float*)d_in[1];
    const float* b1 = (const float*)d_in[2];
    const float* W2 = (const float*)d_in[3];
    // d_in[4] = b2: rank-invariant, unused.
    const int*   kp = (const int*)d_in[5];
    float* out = (float*)d_out;

    // Opt into >48KB dynamic smem (non-stream API: executes immediately,
    // safe under graph capture, allocates nothing). Idempotent.
    static bool attr_set = false;
    if (!attr_set) {
        cudaFuncSetAttribute(scores_kernel,
                             cudaFuncAttributeMaxDynamicSharedMemorySize,
                             SMEM_BYTES);
        attr_set = true;
    }

    scores_kernel<<<BT / FR, 256, SMEM_BYTES>>>(x, W1, b1, W2);
    topk_kernel<<<BB, 256>>>(kp);
    scatter_kernel<<<BT, 128>>>(x, out);
}